// round 10
// baseline (speedup 1.0000x reference)
#include <cuda_runtime.h>
#include <cuda_fp16.h>
#include <cstdint>

// ---------------- problem constants ----------------
#define T_TOKENS 32768
#define E_DIM    512
#define GROUPS   4
#define DIM      128
#define KCODES   512

#define MT       128
#define KT       128
#define THREADS  256

#define MARGIN   4e-3f    // covers fp16 accum worst-case (~2.2e-3) + quant + fp16 store

// ---- smem layout (bytes) ----
#define XH_OFF    0            // 128 rows * 68 u32 = 34816 (half2 x, stride-68 u32)
#define XH_STRIDE 68
#define WH_OFF    34816        // 128 rows * 68 u32 = 34816 (half2 w tile)
#define WH_STRIDE 68
#define S_OFF     69632        // u16 s: 128 * 514 = 131584
#define S_STRIDE16 514
#define WSQ_OFF   201216       // 512*4 = 2048
#define SMIN_OFF  203264       // 128*4 -> 512
#define BK_OFF    203776       // 128*4 -> 512
#define PK_OFF    204288       // 128*8 = 1024
#define RED_OFF   205312       // 8*8 = 64
#define SMEM_TOTAL 205376

__device__ uint32_t g_wh[GROUPS * KCODES * (DIM / 2)];   // packed half2 codebook
__device__ float    g_wsq[GROUPS * KCODES];
__device__ double   g_loss_acc;

__global__ void vq_init_kernel() { g_loss_acc = 0.0; }

__global__ void vq_finalize_kernel(float* out, long long loss_index) {
    out[loss_index] = (float)(g_loss_acc * (1.25 / 4194304.0));
}

// Pack W rows to half2 + exact wsq (sequential fp32 chain, ref order).
__global__ void vq_prep_kernel(const float* __restrict__ w0, const float* __restrict__ w1,
                               const float* __restrict__ w2, const float* __restrict__ w3)
{
    int r = blockIdx.x * blockDim.x + threadIdx.x;
    if (r >= GROUPS * KCODES) return;
    int g = r >> 9, k = r & (KCODES - 1);
    const float* W = (g == 0) ? w0 : (g == 1) ? w1 : (g == 2) ? w2 : w3;
    const float* row = W + (size_t)k * DIM;
    float s = 0.0f;
    #pragma unroll 4
    for (int c = 0; c < DIM / 2; ++c) {
        float a = row[2 * c], b = row[2 * c + 1];
        s = fmaf(a, a, s);
        s = fmaf(b, b, s);
        __half2 h = __floats2half2_rn(a, b);
        g_wh[(size_t)r * (DIM / 2) + c] = *(uint32_t*)&h;
    }
    g_wsq[r] = s;
}

__global__ __launch_bounds__(THREADS, 1)
void vq_main_kernel(const float* __restrict__ latents,
                    const float* __restrict__ w0, const float* __restrict__ w1,
                    const float* __restrict__ w2, const float* __restrict__ w3,
                    float* __restrict__ out)
{
    extern __shared__ char sm[];
    uint32_t* xh      = (uint32_t*)(sm + XH_OFF);
    uint32_t* wh      = (uint32_t*)(sm + WH_OFF);
    uint16_t* s16     = (uint16_t*)(sm + S_OFF);
    float*    wsq_sm  = (float*)(sm + WSQ_OFF);
    float*    smin_sm = (float*)(sm + SMIN_OFF);
    int*      bk_sm   = (int*)(sm + BK_OFF);
    uint64_t* pk_sm   = (uint64_t*)(sm + PK_OFF);
    double*   red     = (double*)(sm + RED_OFF);

    const int g  = blockIdx.y;
    const int t0 = blockIdx.x * MT;
    const float* __restrict__ W = (g == 0) ? w0 : (g == 1) ? w1 : (g == 2) ? w2 : w3;

    const int tid  = threadIdx.x;
    const int wid  = tid >> 5;
    const int lane = tid & 31;
    const int tx   = tid & 15;    // code lane
    const int ty   = tid >> 4;    // token lane

    for (int i = tid; i < KCODES; i += THREADS) wsq_sm[i] = g_wsq[g * KCODES + i];

    // ---- load x tile, convert to half2 pairs in smem ----
    #pragma unroll
    for (int it = 0; it < 16; ++it) {
        int idx = tid + it * THREADS;          // 0..4095 float4s
        int m   = idx >> 5;
        int c4  = idx & 31;
        float4 v = *(const float4*)(latents + (size_t)(t0 + m) * E_DIM + g * DIM + c4 * 4);
        __half2 h0 = __floats2half2_rn(v.x, v.y);
        __half2 h1 = __floats2half2_rn(v.z, v.w);
        uint64_t p = (uint64_t)(*(uint32_t*)&h0) | ((uint64_t)(*(uint32_t*)&h1) << 32);
        *(uint64_t*)(xh + m * XH_STRIDE + c4 * 2) = p;
    }

    // ---- phase A: HFMA2 filter GEMM over 4 code tiles, s -> fp16 smem ----
    for (int kt = 0; kt < 4; ++kt) {
        __syncthreads();   // prior tile's wh readers done
        #pragma unroll
        for (int it = 0; it < 8; ++it) {
            int idx = tid + it * THREADS;      // 0..2047 uint4s
            int r   = idx >> 4;
            int c4  = idx & 15;
            uint4 v = *(const uint4*)(g_wh + ((size_t)(g * KCODES + kt * KT + r)) * (DIM / 2) + c4 * 4);
            *(uint4*)(wh + r * WH_STRIDE + c4 * 4) = v;
        }
        __syncthreads();

        __half2 acc[8][8];
        #pragma unroll
        for (int i = 0; i < 8; ++i)
            #pragma unroll
            for (int j = 0; j < 8; ++j) acc[i][j] = __floats2half2_rn(0.0f, 0.0f);

        #pragma unroll 2
        for (int stp = 0; stp < 16; ++stp) {   // 8 dims (4 half2) per step
            uint4 xv[8];
            #pragma unroll
            for (int i = 0; i < 8; ++i)
                xv[i] = *(const uint4*)(xh + (ty + 16 * i) * XH_STRIDE + stp * 4);
            #pragma unroll
            for (int j = 0; j < 8; ++j) {
                uint4 wv = *(const uint4*)(wh + (tx + 16 * j) * WH_STRIDE + stp * 4);
                const __half2* w2 = (const __half2*)&wv;
                #pragma unroll
                for (int i = 0; i < 8; ++i) {
                    const __half2* x2 = (const __half2*)&xv[i];
                    acc[i][j] = __hfma2(x2[0], w2[0], acc[i][j]);
                    acc[i][j] = __hfma2(x2[1], w2[1], acc[i][j]);
                    acc[i][j] = __hfma2(x2[2], w2[2], acc[i][j]);
                    acc[i][j] = __hfma2(x2[3], w2[3], acc[i][j]);
                }
            }
        }

        // s = wsq - 2*cross_approx -> fp16 store
        #pragma unroll
        for (int j = 0; j < 8; ++j) {
            int k = kt * KT + tx + 16 * j;
            float ws = wsq_sm[k];
            #pragma unroll
            for (int i = 0; i < 8; ++i) {
                float2 f = __half22float2(acc[i][j]);
                float s = fmaf(-2.0f, f.x + f.y, ws);
                __half hh = __float2half_rn(s);
                s16[(ty + 16 * i) * S_STRIDE16 + k] = *(uint16_t*)&hh;
            }
        }
    }
    __syncthreads();

    // ---- phase B: scan + exact candidate refinement (round-6 proven path) ----
    const int t = tid & 127;
    const int h = tid >> 7;
    const uint32_t* srow = (const uint32_t*)s16 + t * (S_STRIDE16 / 2) + h * 128;

    float smin = 3.402823466e38f;
    #pragma unroll 8
    for (int i = 0; i < 128; ++i) {
        __half2 hv = *(const __half2*)(srow + i);
        float2 f = __half22float2(hv);
        smin = fminf(smin, fminf(f.x, f.y));
    }
    if (h == 1) smin_sm[t] = smin;
    __syncthreads();
    if (h == 0) smin_sm[t] = fminf(smin, smin_sm[t]);
    __syncthreads();
    const float thr = smin_sm[t] + MARGIN;

    const float* xrow = latents + (size_t)(t0 + t) * E_DIM + g * DIM;
    float xsq = 0.0f;
    #pragma unroll 4
    for (int d = 0; d < DIM; ++d) xsq = fmaf(xrow[d], xrow[d], xsq);

    uint64_t best = ~0ull;
    for (int i = 0; i < 128; ++i) {
        __half2 hv = *(const __half2*)(srow + i);
        float2 f = __half22float2(hv);
        #pragma unroll
        for (int sub = 0; sub < 2; ++sub) {
            float sv = (sub == 0) ? f.x : f.y;
            if (sv <= thr) {
                int k = h * 256 + i * 2 + sub;
                const float* wr = W + (size_t)k * DIM;
                float cr = 0.0f;
                #pragma unroll 4
                for (int d = 0; d < DIM; ++d) cr = fmaf(xrow[d], wr[d], cr);
                float tt = xsq + wsq_sm[k];          // fl(x_sq + w_sq)
                float dd = fmaf(-2.0f, cr, tt);      // fl(t - 2*cross): exact ref formula
                uint64_t pk = ((uint64_t)__float_as_uint(dd) << 32) | (uint32_t)k;
                best = (pk < best) ? pk : best;
            }
        }
    }
    if (h == 1) pk_sm[t] = best;
    __syncthreads();
    if (h == 0) {
        uint64_t o = pk_sm[t];
        if (o < best) best = o;
        bk_sm[t] = (int)(best & 0xffffffffu);
    }
    __syncthreads();

    // ---- output + loss ----
    double lsum = 0.0;
    #pragma unroll
    for (int it = 0; it < 16; ++it) {
        int idx = tid + it * THREADS;
        int mm  = idx >> 5;
        int c4  = idx & 31;
        int k   = bk_sm[mm];
        float4 q = *(const float4*)(W + (size_t)k * DIM + c4 * 4);
        float4 x = *(const float4*)(latents + (size_t)(t0 + mm) * E_DIM + g * DIM + c4 * 4);
        float dx = q.x - x.x, dy = q.y - x.y, dz = q.z - x.z, dw = q.w - x.w;
        float4 o;
        o.x = x.x + dx; o.y = x.y + dy; o.z = x.z + dz; o.w = x.w + dw;   // x + (q - x), as ref
        *(float4*)(out + (size_t)(t0 + mm) * E_DIM + g * DIM + c4 * 4) = o;
        lsum += (double)dx * dx + (double)dy * dy + (double)dz * dz + (double)dw * dw;
    }
    #pragma unroll
    for (int off = 16; off; off >>= 1)
        lsum += __shfl_xor_sync(0xffffffffu, lsum, off);
    if (lane == 0) red[wid] = lsum;
    __syncthreads();
    if (tid == 0) {
        double s = 0.0;
        #pragma unroll
        for (int w = 0; w < 8; ++w) s += red[w];
        atomicAdd(&g_loss_acc, s);
    }
}

extern "C" void kernel_launch(void* const* d_in, const int* in_sizes, int n_in,
                              void* d_out, int out_size) {
    const float* latents = (const float*)d_in[0];
    const float* w1 = (const float*)d_in[1];
    const float* w2 = (const float*)d_in[2];
    const float* w3 = (const float*)d_in[3];
    const float* w4 = (const float*)d_in[4];
    float* out = (float*)d_out;

    cudaFuncSetAttribute(vq_main_kernel, cudaFuncAttributeMaxDynamicSharedMemorySize, SMEM_TOTAL);

    vq_init_kernel<<<1, 1>>>();
    vq_prep_kernel<<<(GROUPS * KCODES + 255) / 256, 256>>>(w1, w2, w3, w4);
    dim3 grid(T_TOKENS / MT, GROUPS);
    vq_main_kernel<<<grid, THREADS, SMEM_TOTAL>>>(latents, w1, w2, w3, w4, out);
    vq_finalize_kernel<<<1, 1>>>(out, (long long)out_size - 1);
}

// round 11
// speedup vs baseline: 3.0802x; 3.0802x over previous
#include <cuda_runtime.h>
#include <cstdint>

// ---------------- problem constants ----------------
#define T_TOKENS 32768
#define E_DIM    512
#define GROUPS   4
#define DIM      128
#define KCODES   512

#define MT       128
#define KT       128
#define THREADS  256
#define XS_STRIDE 132
#define WS_STRIDE 132

// ---- smem layout (floats/bytes) ----
// xs: 128*132 = 16896 f
// ws: 2 buffers * 128*132 = 33792 f
// wsq: 512 f ; xsq: 128 f
// bestk: 128 int ; red: 8 double
#define SMEM_FLOATS (16896 + 33792 + 512 + 128)
#define SMEM_TOTAL  (SMEM_FLOATS * 4 + 128 * 4 + 8 * 8)

__device__ float  g_wsq[GROUPS * KCODES];
__device__ double g_loss_acc;

__global__ void vq_init_kernel() { g_loss_acc = 0.0; }

__global__ void vq_finalize_kernel(float* out, long long loss_index) {
    out[loss_index] = (float)(g_loss_acc * (1.25 / 4194304.0));
}

// exact wsq per code row (sequential fp32 chain, same order as round-3 in-kernel version)
__global__ void vq_prep_kernel(const float* __restrict__ w0, const float* __restrict__ w1,
                               const float* __restrict__ w2, const float* __restrict__ w3)
{
    int r = blockIdx.x * blockDim.x + threadIdx.x;
    if (r >= GROUPS * KCODES) return;
    int g = r >> 9, k = r & (KCODES - 1);
    const float* W = (g == 0) ? w0 : (g == 1) ? w1 : (g == 2) ? w2 : w3;
    const float* row = W + (size_t)k * DIM;
    float s = 0.0f;
    #pragma unroll 4
    for (int d = 0; d < DIM; ++d) s = fmaf(row[d], row[d], s);
    g_wsq[r] = s;
}

__device__ __forceinline__ uint32_t smem_u32p(const void* p) {
    uint32_t a;
    asm("{ .reg .u64 t; cvta.to.shared.u64 t, %1; cvt.u32.u64 %0, t; }" : "=r"(a) : "l"(p));
    return a;
}
#define CP_ASYNC16(dst_u32, src_ptr) \
    asm volatile("cp.async.cg.shared.global [%0], [%1], 16;" :: "r"(dst_u32), "l"(src_ptr))
#define CP_COMMIT() asm volatile("cp.async.commit_group;" ::: "memory")
#define CP_WAIT0()  asm volatile("cp.async.wait_group 0;" ::: "memory")

__global__ __launch_bounds__(THREADS, 1)
void vq_main_kernel(const float* __restrict__ latents,
                    const float* __restrict__ w0, const float* __restrict__ w1,
                    const float* __restrict__ w2, const float* __restrict__ w3,
                    float* __restrict__ out)
{
    extern __shared__ float smem[];
    float*  xs     = smem;                          // 16896
    float*  ws     = xs + MT * XS_STRIDE;           // 2 * 16896
    float*  wsq_sm = ws + 2 * KT * WS_STRIDE;       // 512
    float*  xsq_sm = wsq_sm + KCODES;               // 128
    int*    bk_sm  = (int*)(xsq_sm + MT);           // 128
    double* red    = (double*)(bk_sm + MT);         // 8

    const int g  = blockIdx.y;
    const int t0 = blockIdx.x * MT;
    const float* __restrict__ W = (g == 0) ? w0 : (g == 1) ? w1 : (g == 2) ? w2 : w3;

    const int tid  = threadIdx.x;
    const int wid  = tid >> 5;
    const int lane = tid & 31;
    const int tx   = tid & 15;    // code lane
    const int ty   = tid >> 4;    // token lane

    const uint32_t ws_base = smem_u32p(ws);

    // ---- prologue: async-load W tile 0 into buffer 0 ----
    {
        #pragma unroll
        for (int it = 0; it < 16; ++it) {
            int idx = tid + it * THREADS;       // 0..4095 16B chunks
            int r   = idx >> 5;
            int c   = idx & 31;
            uint32_t dst = ws_base + (uint32_t)(r * WS_STRIDE + c * 4) * 4u;
            CP_ASYNC16(dst, W + (size_t)r * DIM + c * 4);
        }
        CP_COMMIT();
    }

    // ---- load x tile + wsq ----
    {
        const int d4 = tid & 31;
        const int mb = tid >> 5;
        #pragma unroll
        for (int r = 0; r < MT / 8; ++r) {
            int m = mb + r * 8;
            float4 v = *(const float4*)(latents + (size_t)(t0 + m) * E_DIM + g * DIM + d4 * 4);
            *(float4*)(xs + m * XS_STRIDE + d4 * 4) = v;
        }
    }
    for (int i = tid; i < KCODES; i += THREADS) wsq_sm[i] = g_wsq[g * KCODES + i];
    __syncthreads();

    // xsq per token (sequential fp32 chain, ref order) — overlaps cp.async of tile 0
    if (tid < MT) {
        const float* row = xs + tid * XS_STRIDE;
        float s = 0.0f;
        #pragma unroll
        for (int d = 0; d < DIM; ++d) s = fmaf(row[d], row[d], s);
        xsq_sm[tid] = s;
    }

    float bestd[8];
    int   bestk[8];
    #pragma unroll
    for (int i = 0; i < 8; ++i) { bestd[i] = 3.402823466e38f; bestk[i] = 0; }

    for (int kt = 0; kt < KCODES / KT; ++kt) {
        CP_WAIT0();          // W tile kt resident in buffer kt&1
        __syncthreads();     // also orders xsq writes (kt==0) and frees buffer (kt+1)&1

        // async-prefetch next tile into the other buffer (overlaps compute below)
        if (kt < KCODES / KT - 1) {
            const float* Wn = W + (size_t)(kt + 1) * KT * DIM;
            uint32_t bufb = ws_base + (uint32_t)(((kt + 1) & 1) * KT * WS_STRIDE) * 4u;
            #pragma unroll
            for (int it = 0; it < 16; ++it) {
                int idx = tid + it * THREADS;
                int r   = idx >> 5;
                int c   = idx & 31;
                uint32_t dst = bufb + (uint32_t)(r * WS_STRIDE + c * 4) * 4u;
                CP_ASYNC16(dst, Wn + (size_t)r * DIM + c * 4);
            }
            CP_COMMIT();
        }

        const float* wst = ws + (kt & 1) * KT * WS_STRIDE;

        // ---- 8x8 register-tile dot products (round-3 proven core) ----
        float acc[8][8];
        #pragma unroll
        for (int i = 0; i < 8; ++i)
            #pragma unroll
            for (int j = 0; j < 8; ++j) acc[i][j] = 0.0f;

        for (int d4 = 0; d4 < DIM / 4; ++d4) {
            float4 xf[8];
            #pragma unroll
            for (int i = 0; i < 8; ++i)
                xf[i] = *(const float4*)(xs + (ty + 16 * i) * XS_STRIDE + d4 * 4);
            #pragma unroll
            for (int j = 0; j < 8; ++j) {
                float4 wf = *(const float4*)(wst + (tx + 16 * j) * WS_STRIDE + d4 * 4);
                #pragma unroll
                for (int i = 0; i < 8; ++i) {
                    acc[i][j] = fmaf(xf[i].x, wf.x, acc[i][j]);
                    acc[i][j] = fmaf(xf[i].y, wf.y, acc[i][j]);
                    acc[i][j] = fmaf(xf[i].z, wf.z, acc[i][j]);
                    acc[i][j] = fmaf(xf[i].w, wf.w, acc[i][j]);
                }
            }
        }

        // ---- distances + running argmin (first-index ties; ascending k) ----
        #pragma unroll
        for (int j = 0; j < 8; ++j) {
            int   kk    = kt * KT + tx + 16 * j;
            float t_wsq = wsq_sm[kk];
            #pragma unroll
            for (int i = 0; i < 8; ++i) {
                float t  = xsq_sm[ty + 16 * i] + t_wsq;   // fl(x_sq + w_sq)
                float dd = fmaf(-2.0f, acc[i][j], t);     // fl(t - 2*cross): exact ref formula
                if (dd < bestd[i] || (dd == bestd[i] && kk < bestk[i])) {
                    bestd[i] = dd; bestk[i] = kk;
                }
            }
        }
    }

    // ---- reduce argmin across the 16 code-lanes ----
    #pragma unroll
    for (int i = 0; i < 8; ++i) {
        float bd = bestd[i]; int bk = bestk[i];
        #pragma unroll
        for (int off = 1; off < 16; off <<= 1) {
            float od = __shfl_xor_sync(0xffffffffu, bd, off);
            int   ok = __shfl_xor_sync(0xffffffffu, bk, off);
            if (od < bd || (od == bd && ok < bk)) { bd = od; bk = ok; }
        }
        if (tx == 0) bk_sm[ty + 16 * i] = bk;
    }
    __syncthreads();

    // ---- epilogue: gather codeword, write straight-through output, accumulate loss ----
    double lsum = 0.0;
    #pragma unroll
    for (int r = 0; r < (MT * 32) / THREADS; ++r) {
        int idx = tid + r * THREADS;
        int m   = idx >> 5;
        int c4  = idx & 31;
        int bk  = bk_sm[m];
        float4 q = *(const float4*)(W + (size_t)bk * DIM + c4 * 4);
        float4 x = *(const float4*)(xs + m * XS_STRIDE + c4 * 4);
        float dx = q.x - x.x, dy = q.y - x.y, dz = q.z - x.z, dw = q.w - x.w;
        float4 o;
        o.x = x.x + dx; o.y = x.y + dy; o.z = x.z + dz; o.w = x.w + dw;   // x + (q - x), as ref
        *(float4*)(out + (size_t)(t0 + m) * E_DIM + g * DIM + c4 * 4) = o;
        lsum += (double)dx * dx + (double)dy * dy + (double)dz * dz + (double)dw * dw;
    }
    #pragma unroll
    for (int off = 16; off; off >>= 1)
        lsum += __shfl_xor_sync(0xffffffffu, lsum, off);
    if (lane == 0) red[wid] = lsum;
    __syncthreads();
    if (tid == 0) {
        double s = 0.0;
        #pragma unroll
        for (int w = 0; w < THREADS / 32; ++w) s += red[w];
        atomicAdd(&g_loss_acc, s);
    }
}

extern "C" void kernel_launch(void* const* d_in, const int* in_sizes, int n_in,
                              void* d_out, int out_size) {
    const float* latents = (const float*)d_in[0];
    const float* w1 = (const float*)d_in[1];
    const float* w2 = (const float*)d_in[2];
    const float* w3 = (const float*)d_in[3];
    const float* w4 = (const float*)d_in[4];
    float* out = (float*)d_out;

    cudaFuncSetAttribute(vq_main_kernel, cudaFuncAttributeMaxDynamicSharedMemorySize, SMEM_TOTAL);

    vq_init_kernel<<<1, 1>>>();
    vq_prep_kernel<<<(GROUPS * KCODES + 255) / 256, 256>>>(w1, w2, w3, w4);
    dim3 grid(T_TOKENS / MT, GROUPS);
    vq_main_kernel<<<grid, THREADS, SMEM_TOTAL>>>(latents, w1, w2, w3, w4, out);
    vq_finalize_kernel<<<1, 1>>>(out, (long long)out_size - 1);
}

// round 12
// speedup vs baseline: 3.2092x; 1.0419x over previous
#include <cuda_runtime.h>

// Problem constants
#define T_TOKENS 32768     // 16*2048 tokens
#define E_DIM    512       // embedding dim
#define GROUPS   4
#define DIM      128       // per-group dim
#define KCODES   512       // codes per group

// Tiling
#define MT       128       // tokens per block
#define KT       128       // codes per K-tile
#define THREADS  256
#define XS_STRIDE 132      // padded smem row stride (floats)
#define WS_STRIDE 132

__device__ float  g_wsq[GROUPS * KCODES];
__device__ double g_loss_acc;

__global__ void vq_init_kernel() { g_loss_acc = 0.0; }

__global__ void vq_finalize_kernel(float* out, long long loss_index) {
    // vq_loss = sum_g (beta*commit + embed) = 1.25 * total_sq / (16*2048*128)
    out[loss_index] = (float)(g_loss_acc * (1.25 / 4194304.0));
}

// exact wsq per code row — identical sequential fp32 FMA chain as round-3's
// in-kernel version (same order => bit-identical values => same argmins).
__global__ void vq_prep_kernel(const float* __restrict__ w0, const float* __restrict__ w1,
                               const float* __restrict__ w2, const float* __restrict__ w3)
{
    int r = blockIdx.x * blockDim.x + threadIdx.x;
    if (r >= GROUPS * KCODES) return;
    int g = r >> 9, k = r & (KCODES - 1);
    const float* W = (g == 0) ? w0 : (g == 1) ? w1 : (g == 2) ? w2 : w3;
    const float* row = W + (size_t)k * DIM;
    float s = 0.0f;
    #pragma unroll 4
    for (int d = 0; d < DIM; ++d) s = fmaf(row[d], row[d], s);
    g_wsq[r] = s;
}

__global__ __launch_bounds__(THREADS, 1)
void vq_main_kernel(const float* __restrict__ latents,
                    const float* __restrict__ w0,
                    const float* __restrict__ w1,
                    const float* __restrict__ w2,
                    const float* __restrict__ w3,
                    float* __restrict__ out)
{
    extern __shared__ float smem[];
    float* xs  = smem;                       // MT * XS_STRIDE
    float* ws  = xs + MT * XS_STRIDE;        // KT * WS_STRIDE
    float* xsq = ws + KT * WS_STRIDE;        // MT
    float* wsq = xsq + MT;                   // KCODES (all 512, loaded once)
    int*   bestk_sm = (int*)(wsq + KCODES);  // MT
    double* red = (double*)(bestk_sm + MT);  // 8

    const int g  = blockIdx.y;
    const int t0 = blockIdx.x * MT;
    const float* __restrict__ W = (g == 0) ? w0 : (g == 1) ? w1 : (g == 2) ? w2 : w3;

    const int tid = threadIdx.x;
    const int tx  = tid & 15;   // code lane
    const int ty  = tid >> 4;   // token lane

    // ---- load x tile (tokens t0..t0+127, dims of group g) + wsq ----
    {
        const int d4 = tid & 31;      // float4 index within row
        const int mb = tid >> 5;      // 0..7
        #pragma unroll
        for (int r = 0; r < MT / 8; ++r) {
            int m = mb + r * 8;
            float4 v = *(const float4*)(latents + (size_t)(t0 + m) * E_DIM + g * DIM + d4 * 4);
            *(float4*)(xs + m * XS_STRIDE + d4 * 4) = v;
        }
    }
    for (int i = tid; i < KCODES; i += THREADS) wsq[i] = g_wsq[g * KCODES + i];
    __syncthreads();

    // ---- x_sq per token (sequential fp32, mirrors ref semantics) ----
    if (tid < MT) {
        const float* row = xs + tid * XS_STRIDE;
        float s = 0.0f;
        #pragma unroll
        for (int d = 0; d < DIM; ++d) s = fmaf(row[d], row[d], s);
        xsq[tid] = s;
    }
    __syncthreads();

    // cache this thread's 8 token x_sq values
    float my_xsq[8];
    #pragma unroll
    for (int i = 0; i < 8; ++i) my_xsq[i] = xsq[ty + 16 * i];

    float bestd[8];
    int   bestk[8];
    #pragma unroll
    for (int i = 0; i < 8; ++i) { bestd[i] = 3.402823466e38f; bestk[i] = 0; }

    for (int kt = 0; kt < KCODES / KT; ++kt) {
        __syncthreads();  // previous tile's ws readers done
        // ---- load w tile ----
        {
            const int d4 = tid & 31;
            const int kb = tid >> 5;
            #pragma unroll
            for (int r = 0; r < KT / 8; ++r) {
                int k = kb + r * 8;
                float4 v = *(const float4*)(W + (size_t)(kt * KT + k) * DIM + d4 * 4);
                *(float4*)(ws + k * WS_STRIDE + d4 * 4) = v;
            }
        }
        __syncthreads();

        // ---- 8x8 register-tile dot products ----
        float acc[8][8];
        #pragma unroll
        for (int i = 0; i < 8; ++i)
            #pragma unroll
            for (int j = 0; j < 8; ++j) acc[i][j] = 0.0f;

        for (int d4 = 0; d4 < DIM / 4; ++d4) {
            float4 xf[8];
            #pragma unroll
            for (int i = 0; i < 8; ++i)
                xf[i] = *(const float4*)(xs + (ty + 16 * i) * XS_STRIDE + d4 * 4);
            #pragma unroll
            for (int j = 0; j < 8; ++j) {
                float4 wf = *(const float4*)(ws + (tx + 16 * j) * WS_STRIDE + d4 * 4);
                #pragma unroll
                for (int i = 0; i < 8; ++i) {
                    acc[i][j] = fmaf(xf[i].x, wf.x, acc[i][j]);
                    acc[i][j] = fmaf(xf[i].y, wf.y, acc[i][j]);
                    acc[i][j] = fmaf(xf[i].z, wf.z, acc[i][j]);
                    acc[i][j] = fmaf(xf[i].w, wf.w, acc[i][j]);
                }
            }
        }

        // ---- distances + running argmin (first-index tie break like jnp.argmin) ----
        #pragma unroll
        for (int j = 0; j < 8; ++j) {
            int   kk    = tx + 16 * j;
            int   kg    = kt * KT + kk;
            float t_wsq = wsq[kg];
            #pragma unroll
            for (int i = 0; i < 8; ++i) {
                float t  = my_xsq[i] + t_wsq;           // ref: x_sq + w_sq
                float dd = fmaf(-2.0f, acc[i][j], t);   // == fl(t - 2*cross), matches ref formula
                if (dd < bestd[i] || (dd == bestd[i] && kg < bestk[i])) {
                    bestd[i] = dd; bestk[i] = kg;
                }
            }
        }
    }

    // ---- reduce argmin across the 16 code-lanes ----
    #pragma unroll
    for (int i = 0; i < 8; ++i) {
        float bd = bestd[i]; int bk = bestk[i];
        #pragma unroll
        for (int off = 1; off < 16; off <<= 1) {
            float od = __shfl_xor_sync(0xffffffffu, bd, off);
            int   ok = __shfl_xor_sync(0xffffffffu, bk, off);
            if (od < bd || (od == bd && ok < bk)) { bd = od; bk = ok; }
        }
        if (tx == 0) bestk_sm[ty + 16 * i] = bk;
    }
    __syncthreads();

    // ---- epilogue: gather codeword, write straight-through output, accumulate loss ----
    double lsum = 0.0;
    #pragma unroll
    for (int r = 0; r < (MT * 32) / THREADS; ++r) {  // 16 iters
        int idx = tid + r * THREADS;
        int m   = idx >> 5;
        int d4  = idx & 31;
        int bk  = bestk_sm[m];
        float4 q = *(const float4*)(W + (size_t)bk * DIM + d4 * 4);
        float4 x = *(const float4*)(xs + m * XS_STRIDE + d4 * 4);
        float dx = q.x - x.x, dy = q.y - x.y, dz = q.z - x.z, dw = q.w - x.w;
        float4 o;
        o.x = x.x + dx; o.y = x.y + dy; o.z = x.z + dz; o.w = x.w + dw;  // x + (q - x), as ref
        *(float4*)(out + (size_t)(t0 + m) * E_DIM + g * DIM + d4 * 4) = o;
        lsum += (double)dx * dx + (double)dy * dy + (double)dz * dz + (double)dw * dw;
    }

    // ---- block loss reduction ----
    #pragma unroll
    for (int off = 16; off; off >>= 1)
        lsum += __shfl_xor_sync(0xffffffffu, lsum, off);
    if ((tid & 31) == 0) red[tid >> 5] = lsum;
    __syncthreads();
    if (tid == 0) {
        double s = 0.0;
        #pragma unroll
        for (int w = 0; w < THREADS / 32; ++w) s += red[w];
        atomicAdd(&g_loss_acc, s);
    }
}

extern "C" void kernel_launch(void* const* d_in, const int* in_sizes, int n_in,
                              void* d_out, int out_size) {
    const float* latents = (const float*)d_in[0];
    const float* w1 = (const float*)d_in[1];
    const float* w2 = (const float*)d_in[2];
    const float* w3 = (const float*)d_in[3];
    const float* w4 = (const float*)d_in[4];
    float* out = (float*)d_out;

    // smem: xs + ws + xsq + wsq + bestk + red
    size_t smem_bytes = (size_t)(MT * XS_STRIDE + KT * WS_STRIDE + MT + KCODES) * sizeof(float)
                      + MT * sizeof(int) + 8 * sizeof(double);
    cudaFuncSetAttribute(vq_main_kernel, cudaFuncAttributeMaxDynamicSharedMemorySize,
                         (int)smem_bytes);

    vq_init_kernel<<<1, 1>>>();
    vq_prep_kernel<<<(GROUPS * KCODES + 255) / 256, 256>>>(w1, w2, w3, w4);
    dim3 grid(T_TOKENS / MT, GROUPS);
    vq_main_kernel<<<grid, THREADS, smem_bytes>>>(latents, w1, w2, w3, w4, out);
    vq_finalize_kernel<<<1, 1>>>(out, (long long)out_size - 1);
}